// round 7
// baseline (speedup 1.0000x reference)
#include <cuda_runtime.h>

#define D     4096
#define TPB   256
#define NWARP (TPB / 32)

// Forced re-read (asm volatile so the compiler cannot CSE it with the pass-1
// loads and keep 16 registers alive across barriers).
__device__ __forceinline__ float4 reload4(const float4* p) {
    float4 v;
    asm volatile("ld.global.ca.v4.f32 {%0,%1,%2,%3}, [%4];"
                 : "=f"(v.x), "=f"(v.y), "=f"(v.z), "=f"(v.w)
                 : "l"(p));
    return v;
}

// 50-step bisection, fp32 op-for-op identical to the reference trajectory.
// mask = (sum(Z)-1 >= 0). With p = 1/4095, u^p in [0.975, 1] for every
// positive fp32 u, so mask <=> count(Xs_j > t) >= 2, except count==1 where
// sum = powf(u1,p) can round to >= 1.0f only for u1 within ~1e-4 of 1
// (guard at 0.999f, then evaluate the same libdevice powf).
// Early exit: once t = t_min + diff rounds to t_min, rounding monotonicity
// freezes the trajectory (smaller diff also rounds to t_min) and the
// reference's final t equals t_min.
__device__ __forceinline__ float bisect_t(float Hraw, float Lraw) {
    const float H = __fmul_rn(0.5f, Hraw);   // Xs = 0.5*X, exact & monotone
    const float L = __fmul_rn(0.5f, Lraw);
    const float p = (float)(1.0 / 4095.0);
    float t_min = H - 1.0f;                  // m - 1
    float t_max = H - 0.015625f;             // m - 4096^(1-1.5)
    float diff  = t_max - t_min;
    float t     = t_min;
    #pragma unroll 1
    for (int it = 0; it < 50; it++) {
        diff *= 0.5f;
        t = t_min + diff;
        if (t == t_min) break;               // frozen: final t == t_min
        bool mask;
        if (t < L) {
            mask = true;                     // >=2 positive terms -> sum >= 1.95
        } else {
            float u1 = H - t;
            mask = (u1 >= 0.999f) ? (powf(u1, p) >= 1.0f) : false;
        }
        if (mask) t_min = t;
    }
    return t;
}

__global__ __launch_bounds__(TPB, 8)
void entmax_bisect_kernel(const float* __restrict__ X, float* __restrict__ Y) {
    const int tid  = threadIdx.x;
    const int lane = tid & 31;
    const int wid  = tid >> 5;
    const size_t base = (size_t)blockIdx.x * D;

    __shared__ float s_h[NWARP], s_l[NWARP], s_s[NWARP];
    __shared__ float s_t;

    const float4* Xv = reinterpret_cast<const float4*>(X + base);
    float4*       Yv = reinterpret_cast<float4*>(Y + base);

    // ---- Pass 0: fire the entire zero write stream NOW (no dependencies).
    // Final output is zero everywhere except 1-3 entries per row; the hot
    // threads overwrite their own vectors in the epilogue (same thread, same
    // addresses -> program order guarantees the overwrite lands last). ----
    const float4 zero4 = make_float4(0.0f, 0.0f, 0.0f, 0.0f);
    __stcs(Yv + tid,           zero4);
    __stcs(Yv + TPB + tid,     zero4);
    __stcs(Yv + 2 * TPB + tid, zero4);
    __stcs(Yv + 3 * TPB + tid, zero4);

    // ---- Pass 1: load 16 values, fold into top-2, DROP the values ----
    float hi, lo = -3.402823466e38f;
    {
        float4 f0 = Xv[tid];
        float4 f1 = Xv[TPB + tid];
        float4 f2 = Xv[2 * TPB + tid];
        float4 f3 = Xv[3 * TPB + tid];
        float v;
        hi = f0.x;
        v = f0.y; lo = fmaxf(lo, fminf(hi, v)); hi = fmaxf(hi, v);
        v = f0.z; lo = fmaxf(lo, fminf(hi, v)); hi = fmaxf(hi, v);
        v = f0.w; lo = fmaxf(lo, fminf(hi, v)); hi = fmaxf(hi, v);
        v = f1.x; lo = fmaxf(lo, fminf(hi, v)); hi = fmaxf(hi, v);
        v = f1.y; lo = fmaxf(lo, fminf(hi, v)); hi = fmaxf(hi, v);
        v = f1.z; lo = fmaxf(lo, fminf(hi, v)); hi = fmaxf(hi, v);
        v = f1.w; lo = fmaxf(lo, fminf(hi, v)); hi = fmaxf(hi, v);
        v = f2.x; lo = fmaxf(lo, fminf(hi, v)); hi = fmaxf(hi, v);
        v = f2.y; lo = fmaxf(lo, fminf(hi, v)); hi = fmaxf(hi, v);
        v = f2.z; lo = fmaxf(lo, fminf(hi, v)); hi = fmaxf(hi, v);
        v = f2.w; lo = fmaxf(lo, fminf(hi, v)); hi = fmaxf(hi, v);
        v = f3.x; lo = fmaxf(lo, fminf(hi, v)); hi = fmaxf(hi, v);
        v = f3.y; lo = fmaxf(lo, fminf(hi, v)); hi = fmaxf(hi, v);
        v = f3.z; lo = fmaxf(lo, fminf(hi, v)); hi = fmaxf(hi, v);
        v = f3.w; lo = fmaxf(lo, fminf(hi, v)); hi = fmaxf(hi, v);
    }
    const float thi = hi;                    // per-thread raw max

    // ---- Warp butterfly top-2 ----
    #pragma unroll
    for (int off = 16; off > 0; off >>= 1) {
        float oh = __shfl_xor_sync(0xffffffffu, hi, off);
        float ol = __shfl_xor_sync(0xffffffffu, lo, off);
        float nh = fmaxf(hi, oh);
        lo = fmaxf(fmaxf(lo, ol), fminf(hi, oh));
        hi = nh;
    }
    if (lane == 0) { s_h[wid] = hi; s_l[wid] = lo; }
    __syncthreads();                                      // b1

    // ---- Thread 0: combine warps' top-2 + scalar bisection ----
    if (tid == 0) {
        float H = s_h[0], L = s_l[0];
        #pragma unroll
        for (int w = 1; w < NWARP; w++) {
            float oh = s_h[w], ol = s_l[w];
            float nh = fmaxf(H, oh);
            L = fmaxf(fmaxf(L, ol), fminf(H, oh));
            H = nh;
        }
        s_t = bisect_t(H, L);
    }
    __syncthreads();                                      // b2

    const float t = s_t;
    const float p = (float)(1.0 / 4095.0);
    const bool hot = (__fmul_rn(0.5f, thi) > t);          // exact: x0.5 monotone

    // ---- Pass 2 (hot threads only, ~1-3 per row): re-read (L1 hit), sum z ----
    float sum = 0.0f;
    if (hot) {
        #pragma unroll
        for (int k = 0; k < 4; k++) {
            float4 g = reload4(Xv + k * TPB + tid);
            float u;
            u = __fmul_rn(0.5f, g.x) - t; if (u > 0.0f) sum += powf(u, p);
            u = __fmul_rn(0.5f, g.y) - t; if (u > 0.0f) sum += powf(u, p);
            u = __fmul_rn(0.5f, g.z) - t; if (u > 0.0f) sum += powf(u, p);
            u = __fmul_rn(0.5f, g.w) - t; if (u > 0.0f) sum += powf(u, p);
        }
    }
    #pragma unroll
    for (int off = 16; off > 0; off >>= 1)
        sum += __shfl_xor_sync(0xffffffffu, sum, off);
    if (lane == 0) s_s[wid] = sum;
    __syncthreads();                                      // b3

    float S = 0.0f;
    #pragma unroll
    for (int w = 0; w < NWARP; w++) S += s_s[w];

    // ---- Epilogue: only hot threads overwrite their (already-zeroed) spans ----
    if (hot) {
        const float rinv = 1.0f / S;                      // S > 0 always
        #pragma unroll
        for (int k = 0; k < 4; k++) {
            float4 g = reload4(Xv + k * TPB + tid);       // L1 hit
            float4 o = zero4;
            float u;
            u = __fmul_rn(0.5f, g.x) - t; if (u > 0.0f) o.x = powf(u, p) * rinv;
            u = __fmul_rn(0.5f, g.y) - t; if (u > 0.0f) o.y = powf(u, p) * rinv;
            u = __fmul_rn(0.5f, g.z) - t; if (u > 0.0f) o.z = powf(u, p) * rinv;
            u = __fmul_rn(0.5f, g.w) - t; if (u > 0.0f) o.w = powf(u, p) * rinv;
            __stcs(Yv + k * TPB + tid, o);
        }
    }
}

extern "C" void kernel_launch(void* const* d_in, const int* in_sizes, int n_in,
                              void* d_out, int out_size) {
    const float* X = (const float*)d_in[0];
    float* Y = (float*)d_out;
    const int rows = in_sizes[0] / D;                     // 16384
    entmax_bisect_kernel<<<rows, TPB>>>(X, Y);
}